// round 11
// baseline (speedup 1.0000x reference)
#include <cuda_runtime.h>
#include <cstdint>

// ---------------------------------------------------------------------------
// B=512, N=256, H=128
//   A2 = A[:,:,:256] + A[:,:,256:],  d_i = rsqrt(rowsum(A2)+1)
//   A_mix = 0.8*D*A2*D + diag(c),    c_i = 0.1 + d_i^2*(0.7 - 0.1*A2_ii)
//   out = A_mix @ (A_mix @ emb[idx])
// Z-space: Z0 = D*emb[idx]; Z1 = 0.8 d^2 (A2@Z0) + c.*Z0;
//          out = 0.8 d (A2@Z1) + (c/d).*Z1
//
// Engine: legacy mma.sync m16n8k8 tf32, free-running warps (no mainloop
// barriers). A2 fragment-permuted in gmem (L2-resident), 2-k8-ahead register
// prefetch. Warp tile 64x64 (1.0 L1-wavefront/MMA vs 1.5 at 64x32).
// Grid (2 h-halves, 512 batches), 128 thr (4 warps, 4m x 1n), 2 CTAs/SM.
//   A2p per batch: [k8 32][mblk 16][lane 32] float4
//   Z: smem pair-interleaved: slot(k8,t) = (Z[k8*8+t], Z[k8*8+t+4]) per h col
// ---------------------------------------------------------------------------

#define Bsz 512
#define Nn  256
#define Hh  128
#define NNODE 50000

__device__ float g_A2p[(size_t)Bsz * Nn * Nn];   // fragment-permuted tf32
__device__ float g_d  [(size_t)Bsz * Nn];
__device__ float g_c  [(size_t)Bsz * Nn];

__device__ __forceinline__ float to_tf32(float x) {
    uint32_t u;
    asm("cvt.rna.tf32.f32 %0, %1;" : "=r"(u) : "f"(x));
    return __uint_as_float(u);
}

// ---------------------------------------------------------------------------
// prep: 16-row slab per block. d, c, fragment-permuted tf32 A2 image
// (k8-major). grid (16, 512), block 256.
// ---------------------------------------------------------------------------
__global__ __launch_bounds__(256)
void prep_kernel(const float* __restrict__ A) {
    __shared__ float s2[16 * 260];
    const int b    = blockIdx.y;
    const int mblk = blockIdx.x;
    const int t    = threadIdx.x;
    const int i0   = mblk * 16;

    #pragma unroll
    for (int p = 0; p < 4; p++) {
        int fidx = t + p * 256;
        int row  = fidx >> 6;
        int c4   = fidx & 63;
        const float4* src =
            (const float4*)(A + ((size_t)(b * Nn + i0 + row)) * (2 * Nn));
        float4 a  = src[c4];
        float4 bb = src[c4 + 64];
        *(float4*)(s2 + row * 260 + c4 * 4) =
            make_float4(a.x + bb.x, a.y + bb.y, a.z + bb.z, a.w + bb.w);
    }
    __syncthreads();

    const int lane = t & 31, w = t >> 5;
    #pragma unroll
    for (int rr = 0; rr < 2; rr++) {
        int row = w * 2 + rr;
        float s = 0.0f;
        #pragma unroll
        for (int k = 0; k < 8; k++) s += s2[row * 260 + lane + 32 * k];
        #pragma unroll
        for (int o = 16; o; o >>= 1) s += __shfl_xor_sync(0xFFFFFFFFu, s, o);
        if (lane == 0) {
            int i = i0 + row;
            float aii = s2[row * 260 + i];
            float d = rsqrtf(s + 1.0f);
            g_d[b * Nn + i] = d;
            g_c[b * Nn + i] = 0.1f + d * d * (0.7f - 0.1f * aii);
        }
    }

    // fragment-permuted, k8-major write: dst[k8*512 + mblk*32 + lane]
    float4* dst = (float4*)g_A2p + (size_t)b * 16384;
    #pragma unroll
    for (int p = 0; p < 4; p++) {
        int q    = t + p * 256;
        int k8   = q >> 5;
        int lp   = q & 31;
        int gr2  = lp >> 2, tc2 = lp & 3;
        int col  = k8 * 8;
        float e0 = s2[(gr2    ) * 260 + col + tc2    ];
        float e1 = s2[(gr2 + 8) * 260 + col + tc2    ];
        float e2 = s2[(gr2    ) * 260 + col + tc2 + 4];
        float e3 = s2[(gr2 + 8) * 260 + col + tc2 + 4];
        dst[k8 * 512 + mblk * 32 + lp] =
            make_float4(to_tf32(e0), to_tf32(e1), to_tf32(e2), to_tf32(e3));
    }
}

// ---------------------------------------------------------------------------
__device__ __forceinline__ void mma_tf32(float* c, const uint32_t* a, const uint32_t* b) {
    asm volatile(
        "mma.sync.aligned.m16n8k8.row.col.f32.tf32.tf32.f32 "
        "{%0,%1,%2,%3}, {%4,%5,%6,%7}, {%8,%9}, {%0,%1,%2,%3};\n"
        : "+f"(c[0]), "+f"(c[1]), "+f"(c[2]), "+f"(c[3])
        : "r"(a[0]), "r"(a[1]), "r"(a[2]), "r"(a[3]),
          "r"(b[0]), "r"(b[1]));
}

// ---------------------------------------------------------------------------
// Fused kernel. grid (2, 512), block 128 (4 warps: 4m x 1n, warp tile 64x64).
// smem: Z pairs 68KB + d/c 2KB -> 2 CTAs/SM (8 warps/SM, ~195 regs/thr).
// ---------------------------------------------------------------------------
#define ZP_STRIDE 68
#define SZ_FLOATS (128 * ZP_STRIDE * 2)
#define SMEM_FLOATS (SZ_FLOATS + 2 * 256)

__global__ __launch_bounds__(128, 2)
void sgc_fused(const void* __restrict__ idx_raw,
               const float* __restrict__ emb,
               float* __restrict__ out) {
    extern __shared__ float smem[];
    float* sZ = smem;
    float* sd = smem + SZ_FLOATS;
    float* sc = sd + 256;

    const int half = blockIdx.x;
    const int b    = blockIdx.y;
    const int tid  = threadIdx.x;
    const int lane = tid & 31;
    const int wm   = tid >> 5;      // 4 m-blocks of 64
    const int gr   = lane >> 2;
    const int tc   = lane & 3;

    // index dtype detection (true int64 indices < 50000 -> high words zero)
    const unsigned long long* iq = (const unsigned long long*)idx_raw;
    int is64 = 1;
    #pragma unroll
    for (int i = 0; i < 16; i++)
        if (iq[i] >> 32) is64 = 0;

    sd[tid]       = g_d[b * Nn + tid];
    sd[tid + 128] = g_d[b * Nn + tid + 128];
    sc[tid]       = g_c[b * Nn + tid];
    sc[tid + 128] = g_c[b * Nn + tid + 128];
    __syncthreads();

    // Z0 gather: thread <-> k row (2 blocks of 128); this half's 64 emb cols
    #pragma unroll
    for (int kb = 0; kb < 2; kb++) {
        const int k = kb * 128 + tid;
        long long node = is64 ? ((const long long*)idx_raw)[b * Nn + k]
                              : (long long)((const int*)idx_raw)[b * Nn + k];
        if (node < 0) node = 0;
        if (node >= NNODE) node = NNODE - 1;
        const float dk = sd[k];
        const int slot = (k >> 3) * 4 + (k & 3);
        const int comp = (k >> 2) & 1;
        float* zrow = sZ + slot * (ZP_STRIDE * 2) + comp;
        const float4* src = (const float4*)(emb + (size_t)node * Hh + half * 64);
        #pragma unroll
        for (int j = 0; j < 16; j++) {
            float4 v = src[j];
            const int h = j * 4;
            zrow[(h    ) * 2] = to_tf32(dk * v.x);
            zrow[(h + 1) * 2] = to_tf32(dk * v.y);
            zrow[(h + 2) * 2] = to_tf32(dk * v.z);
            zrow[(h + 3) * 2] = to_tf32(dk * v.w);
        }
    }
    __syncthreads();

    const float4* __restrict__ A2f4 =
        (const float4*)g_A2p + (size_t)b * 16384 + (wm * 4) * 32 + lane;

    float acc[4][8][4];
    auto zero_acc = [&]() {
        #pragma unroll
        for (int mt = 0; mt < 4; mt++)
            #pragma unroll
            for (int nt = 0; nt < 8; nt++)
                #pragma unroll
                for (int e = 0; e < 4; e++) acc[mt][nt][e] = 0.0f;
    };

    // free-running mainloop, 2-k8-ahead register prefetch, no barriers
    auto run_round = [&]() {
        float4 abuf[2][4];
        #pragma unroll
        for (int mt = 0; mt < 4; mt++) {
            abuf[0][mt] = __ldg(A2f4 + mt * 32);            // k8 = 0
            abuf[1][mt] = __ldg(A2f4 + 512 + mt * 32);      // k8 = 1
        }

        #pragma unroll 2
        for (int k8 = 0; k8 < 32; k8++) {
            const int cur = k8 & 1;
            uint32_t af[4][4];
            #pragma unroll
            for (int mt = 0; mt < 4; mt++) {
                af[mt][0] = __float_as_uint(abuf[cur][mt].x);
                af[mt][1] = __float_as_uint(abuf[cur][mt].y);
                af[mt][2] = __float_as_uint(abuf[cur][mt].z);
                af[mt][3] = __float_as_uint(abuf[cur][mt].w);
            }
            if (k8 < 30) {
                const float4* nsrc = A2f4 + (k8 + 2) * 512;
                #pragma unroll
                for (int mt = 0; mt < 4; mt++)
                    abuf[cur][mt] = __ldg(nsrc + mt * 32);
            }
            #pragma unroll
            for (int nt = 0; nt < 8; nt++) {
                const int cb = nt * 8 + gr;
                float2 bv = *(const float2*)(sZ +
                            ((k8 * 4 + tc) * ZP_STRIDE + cb) * 2);
                uint32_t bf[2];
                bf[0] = __float_as_uint(bv.x);
                bf[1] = __float_as_uint(bv.y);
                #pragma unroll
                for (int mt = 0; mt < 4; mt++)
                    mma_tf32(acc[mt][nt], af[mt], bf);
            }
        }
    };

    // ================= round 0 =================
    zero_acc();
    run_round();

    __syncthreads();   // all warps done READING sZ before rewrite

    // epilogue 0: Z1 = tf32(0.8 d^2 W0 + c Z0), in place
    #pragma unroll
    for (int mt = 0; mt < 4; mt++) {
        #pragma unroll
        for (int rr = 0; rr < 2; rr++) {
            const int r = wm * 64 + mt * 16 + gr + rr * 8;
            const float ws = 0.8f * sd[r] * sd[r];
            const float cc = sc[r];
            float* base = sZ + ((r >> 3) * 4 + (r & 3)) * (ZP_STRIDE * 2)
                             + ((r >> 2) & 1);
            #pragma unroll
            for (int nt = 0; nt < 8; nt++) {
                const int col = nt * 8 + tc * 2;
                float z0 = base[(col    ) * 2];
                float z1 = base[(col + 1) * 2];
                base[(col    ) * 2] = to_tf32(ws * acc[mt][nt][rr * 2 + 0] + cc * z0);
                base[(col + 1) * 2] = to_tf32(ws * acc[mt][nt][rr * 2 + 1] + cc * z1);
            }
        }
    }
    __syncthreads();

    // ================= round 1 =================
    zero_acc();
    run_round();

    // epilogue 1: out = 0.8 d W1 + (c/d) Z1   (sZ read-only here)
    float* __restrict__ dstb = out + (size_t)b * Nn * Hh + half * 64;
    #pragma unroll
    for (int mt = 0; mt < 4; mt++) {
        #pragma unroll
        for (int rr = 0; rr < 2; rr++) {
            const int r = wm * 64 + mt * 16 + gr + rr * 8;
            const float dk = sd[r];
            const float ws = 0.8f * dk;
            const float zs = sc[r] / dk;
            const float* base = sZ + ((r >> 3) * 4 + (r & 3)) * (ZP_STRIDE * 2)
                                   + ((r >> 2) & 1);
            #pragma unroll
            for (int nt = 0; nt < 8; nt++) {
                const int col = nt * 8 + tc * 2;
                float o0 = ws * acc[mt][nt][rr * 2 + 0] + zs * base[(col    ) * 2];
                float o1 = ws * acc[mt][nt][rr * 2 + 1] + zs * base[(col + 1) * 2];
                *(float2*)(dstb + (size_t)r * Hh + col) = make_float2(o0, o1);
            }
        }
    }
}

// ---------------------------------------------------------------------------
extern "C" void kernel_launch(void* const* d_in, const int* in_sizes, int n_in,
                              void* d_out, int out_size) {
    const void*  inputs = nullptr;
    const float* A      = nullptr;
    const float* emb    = nullptr;

    for (int i = 0; i < n_in; ++i) {
        if (in_sizes[i] == Bsz * Nn)               inputs = d_in[i];
        else if (in_sizes[i] == Bsz * Nn * 2 * Nn) A      = (const float*)d_in[i];
        else if (in_sizes[i] == NNODE * Hh)        emb    = (const float*)d_in[i];
    }
    if (!inputs) inputs = d_in[0];
    if (!A)      A      = (const float*)d_in[1];
    if (!emb)    emb    = (const float*)d_in[2];

    float* out = (float*)d_out;

    static bool attr_set = false;
    const int smem_bytes = SMEM_FLOATS * sizeof(float);   // 71,680 B
    if (!attr_set) {
        cudaFuncSetAttribute(sgc_fused, cudaFuncAttributeMaxDynamicSharedMemorySize,
                             smem_bytes);
        attr_set = true;
    }

    prep_kernel<<<dim3(16, Bsz), 256>>>(A);
    sgc_fused<<<dim3(2, Bsz), 128, smem_bytes>>>(inputs, emb, out);
}

// round 12
// speedup vs baseline: 1.0222x; 1.0222x over previous
#include <cuda_runtime.h>
#include <cstdint>

// ---------------------------------------------------------------------------
// B=512, N=256, H=128
//   A2 = A[:,:,:256] + A[:,:,256:],  d_i = rsqrt(rowsum(A2)+1)
//   A_mix = 0.8*D*A2*D + diag(c),    c_i = 0.1 + d_i^2*(0.7 - 0.1*A2_ii)
//   out = A_mix @ (A_mix @ emb[idx])
// Z-space: Z0 = D*emb[idx]; Z1 = 0.8 d^2 (A2@Z0) + c.*Z0;
//          out = 0.8 d (A2@Z1) + (c/d).*Z1
//
// Engine: legacy mma.sync m16n8k8 tf32, free-running warps (no mainloop
// barriers). A2 fragment-permuted in gmem (L2-resident), 1-k8-ahead register
// prefetch + 3-k8-ahead prefetch.global.L1 (turns consuming LDG into L1 hit).
// Grid (2 h-halves, 512 batches), 256 thr (8 warps: 4m x 2n, tile 64x32),
// 2 CTAs/SM -> 16 warps/SM.
//   A2p per batch: [k8 32][mblk 16][lane 32] float4
//   Z: smem pair-interleaved: slot(k8,t) = (Z[k8*8+t], Z[k8*8+t+4]) per h col
// ---------------------------------------------------------------------------

#define Bsz 512
#define Nn  256
#define Hh  128
#define NNODE 50000

__device__ float g_A2p[(size_t)Bsz * Nn * Nn];   // fragment-permuted tf32
__device__ float g_d  [(size_t)Bsz * Nn];
__device__ float g_c  [(size_t)Bsz * Nn];

__device__ __forceinline__ float to_tf32(float x) {
    uint32_t u;
    asm("cvt.rna.tf32.f32 %0, %1;" : "=r"(u) : "f"(x));
    return __uint_as_float(u);
}

// ---------------------------------------------------------------------------
// prep: 16-row slab per block. d, c, fragment-permuted tf32 A2 image
// (k8-major). grid (16, 512), block 256.
// ---------------------------------------------------------------------------
__global__ __launch_bounds__(256)
void prep_kernel(const float* __restrict__ A) {
    __shared__ float s2[16 * 260];
    const int b    = blockIdx.y;
    const int mblk = blockIdx.x;
    const int t    = threadIdx.x;
    const int i0   = mblk * 16;

    #pragma unroll
    for (int p = 0; p < 4; p++) {
        int fidx = t + p * 256;
        int row  = fidx >> 6;
        int c4   = fidx & 63;
        const float4* src =
            (const float4*)(A + ((size_t)(b * Nn + i0 + row)) * (2 * Nn));
        float4 a  = src[c4];
        float4 bb = src[c4 + 64];
        *(float4*)(s2 + row * 260 + c4 * 4) =
            make_float4(a.x + bb.x, a.y + bb.y, a.z + bb.z, a.w + bb.w);
    }
    __syncthreads();

    const int lane = t & 31, w = t >> 5;
    #pragma unroll
    for (int rr = 0; rr < 2; rr++) {
        int row = w * 2 + rr;
        float s = 0.0f;
        #pragma unroll
        for (int k = 0; k < 8; k++) s += s2[row * 260 + lane + 32 * k];
        #pragma unroll
        for (int o = 16; o; o >>= 1) s += __shfl_xor_sync(0xFFFFFFFFu, s, o);
        if (lane == 0) {
            int i = i0 + row;
            float aii = s2[row * 260 + i];
            float d = rsqrtf(s + 1.0f);
            g_d[b * Nn + i] = d;
            g_c[b * Nn + i] = 0.1f + d * d * (0.7f - 0.1f * aii);
        }
    }

    // fragment-permuted, k8-major write: dst[k8*512 + mblk*32 + lane]
    float4* dst = (float4*)g_A2p + (size_t)b * 16384;
    #pragma unroll
    for (int p = 0; p < 4; p++) {
        int q    = t + p * 256;
        int k8   = q >> 5;
        int lp   = q & 31;
        int gr2  = lp >> 2, tc2 = lp & 3;
        int col  = k8 * 8;
        float e0 = s2[(gr2    ) * 260 + col + tc2    ];
        float e1 = s2[(gr2 + 8) * 260 + col + tc2    ];
        float e2 = s2[(gr2    ) * 260 + col + tc2 + 4];
        float e3 = s2[(gr2 + 8) * 260 + col + tc2 + 4];
        dst[k8 * 512 + mblk * 32 + lp] =
            make_float4(to_tf32(e0), to_tf32(e1), to_tf32(e2), to_tf32(e3));
    }
}

// ---------------------------------------------------------------------------
__device__ __forceinline__ void mma_tf32(float* c, const uint32_t* a, const uint32_t* b) {
    asm volatile(
        "mma.sync.aligned.m16n8k8.row.col.f32.tf32.tf32.f32 "
        "{%0,%1,%2,%3}, {%4,%5,%6,%7}, {%8,%9}, {%0,%1,%2,%3};\n"
        : "+f"(c[0]), "+f"(c[1]), "+f"(c[2]), "+f"(c[3])
        : "r"(a[0]), "r"(a[1]), "r"(a[2]), "r"(a[3]),
          "r"(b[0]), "r"(b[1]));
}

__device__ __forceinline__ void prefetch_l1(const void* p) {
    asm volatile("prefetch.global.L1 [%0];" :: "l"(p));
}

// ---------------------------------------------------------------------------
// Fused kernel. grid (2, 512), block 256 (8 warps: 4m x 2n, warp tile 64x32).
// smem: Z pairs 68KB + d/c 2KB -> 2 CTAs/SM, 16 warps/SM.
// ---------------------------------------------------------------------------
#define ZP_STRIDE 68                     // pair-units per tc-row (mod 16 == 4)
#define SZ_FLOATS (128 * ZP_STRIDE * 2)  // 17408 floats
#define SMEM_FLOATS (SZ_FLOATS + 2 * 256)

__global__ __launch_bounds__(256, 2)
void sgc_fused(const void* __restrict__ idx_raw,
               const float* __restrict__ emb,
               float* __restrict__ out) {
    extern __shared__ float smem[];
    float* sZ = smem;
    float* sd = smem + SZ_FLOATS;
    float* sc = sd + 256;

    const int half = blockIdx.x;
    const int b    = blockIdx.y;
    const int tid  = threadIdx.x;
    const int lane = tid & 31;
    const int w    = tid >> 5;
    const int wm   = w & 3;
    const int wn   = w >> 2;
    const int gr   = lane >> 2;
    const int tc   = lane & 3;

    // index dtype detection (true int64 indices < 50000 -> high words zero)
    const unsigned long long* iq = (const unsigned long long*)idx_raw;
    int is64 = 1;
    #pragma unroll
    for (int i = 0; i < 16; i++)
        if (iq[i] >> 32) is64 = 0;

    sd[tid] = g_d[b * Nn + tid];
    sc[tid] = g_c[b * Nn + tid];
    __syncthreads();

    // Z0 gather: thread <-> k row; this half's 64 emb columns
    {
        const int k = tid;
        long long node = is64 ? ((const long long*)idx_raw)[b * Nn + k]
                              : (long long)((const int*)idx_raw)[b * Nn + k];
        if (node < 0) node = 0;
        if (node >= NNODE) node = NNODE - 1;
        const float dk = sd[k];
        const int slot = (k >> 3) * 4 + (k & 3);
        const int comp = (k >> 2) & 1;
        float* zrow = sZ + slot * (ZP_STRIDE * 2) + comp;
        const float4* src = (const float4*)(emb + (size_t)node * Hh + half * 64);
        #pragma unroll
        for (int j = 0; j < 16; j++) {
            float4 v = src[j];
            const int h = j * 4;
            zrow[(h    ) * 2] = to_tf32(dk * v.x);
            zrow[(h + 1) * 2] = to_tf32(dk * v.y);
            zrow[(h + 2) * 2] = to_tf32(dk * v.z);
            zrow[(h + 3) * 2] = to_tf32(dk * v.w);
        }
    }
    __syncthreads();

    const float4* __restrict__ A2f4 =
        (const float4*)g_A2p + (size_t)b * 16384 + (wm * 4) * 32 + lane;

    float acc[4][4][4];
    auto zero_acc = [&]() {
        #pragma unroll
        for (int mt = 0; mt < 4; mt++)
            #pragma unroll
            for (int nt = 0; nt < 4; nt++)
                #pragma unroll
                for (int e = 0; e < 4; e++) acc[mt][nt][e] = 0.0f;
    };

    // free-running mainloop: no barriers. 1-k8-ahead register buffer +
    // 3-k8-ahead L1 prefetch (consuming LDG becomes an L1 hit).
    auto run_round = [&]() {
        float4 abuf[2][4];
        #pragma unroll
        for (int mt = 0; mt < 4; mt++) {
            abuf[0][mt] = __ldg(A2f4 + mt * 32);
            prefetch_l1(A2f4 + 512 + mt * 32);       // k8=1
            prefetch_l1(A2f4 + 2 * 512 + mt * 32);   // k8=2
        }

        #pragma unroll 2
        for (int k8 = 0; k8 < 32; k8++) {
            const int cur = k8 & 1;
            if (k8 < 31) {
                const float4* nsrc = A2f4 + (k8 + 1) * 512;
                #pragma unroll
                for (int mt = 0; mt < 4; mt++)
                    abuf[cur ^ 1][mt] = __ldg(nsrc + mt * 32);
            }
            if (k8 < 29) {
                const float4* pf = A2f4 + (k8 + 3) * 512;
                #pragma unroll
                for (int mt = 0; mt < 4; mt++)
                    prefetch_l1(pf + mt * 32);
            }
            uint32_t bf[4][2];
            #pragma unroll
            for (int nt = 0; nt < 4; nt++) {
                const int cb = wn * 32 + nt * 8 + gr;
                float2 bv = *(const float2*)(sZ +
                            ((k8 * 4 + tc) * ZP_STRIDE + cb) * 2);
                bf[nt][0] = __float_as_uint(bv.x);
                bf[nt][1] = __float_as_uint(bv.y);
            }
            #pragma unroll
            for (int mt = 0; mt < 4; mt++) {
                uint32_t af[4];
                af[0] = __float_as_uint(abuf[cur][mt].x);
                af[1] = __float_as_uint(abuf[cur][mt].y);
                af[2] = __float_as_uint(abuf[cur][mt].z);
                af[3] = __float_as_uint(abuf[cur][mt].w);
                #pragma unroll
                for (int nt = 0; nt < 4; nt++)
                    mma_tf32(acc[mt][nt], af, bf[nt]);
            }
        }
    };

    // ================= round 0 =================
    zero_acc();
    run_round();

    __syncthreads();   // all warps done READING sZ before it is rewritten

    // epilogue 0: Z1 = tf32(0.8 d^2 W0 + c Z0), in place
    #pragma unroll
    for (int mt = 0; mt < 4; mt++) {
        #pragma unroll
        for (int rr = 0; rr < 2; rr++) {
            const int r = wm * 64 + mt * 16 + gr + rr * 8;
            const float ws = 0.8f * sd[r] * sd[r];
            const float cc = sc[r];
            float* base = sZ + ((r >> 3) * 4 + (r & 3)) * (ZP_STRIDE * 2)
                             + ((r >> 2) & 1);
            #pragma unroll
            for (int nt = 0; nt < 4; nt++) {
                const int col = wn * 32 + nt * 8 + tc * 2;
                float z0 = base[(col    ) * 2];
                float z1 = base[(col + 1) * 2];
                base[(col    ) * 2] = to_tf32(ws * acc[mt][nt][rr * 2 + 0] + cc * z0);
                base[(col + 1) * 2] = to_tf32(ws * acc[mt][nt][rr * 2 + 1] + cc * z1);
            }
        }
    }
    __syncthreads();

    // ================= round 1 =================
    zero_acc();
    run_round();

    // epilogue 1: out = 0.8 d W1 + (c/d) Z1   (sZ read-only here)
    float* __restrict__ dstb = out + (size_t)b * Nn * Hh + half * 64;
    #pragma unroll
    for (int mt = 0; mt < 4; mt++) {
        #pragma unroll
        for (int rr = 0; rr < 2; rr++) {
            const int r = wm * 64 + mt * 16 + gr + rr * 8;
            const float dk = sd[r];
            const float ws = 0.8f * dk;
            const float zs = sc[r] / dk;
            const float* base = sZ + ((r >> 3) * 4 + (r & 3)) * (ZP_STRIDE * 2)
                                   + ((r >> 2) & 1);
            #pragma unroll
            for (int nt = 0; nt < 4; nt++) {
                const int col = wn * 32 + nt * 8 + tc * 2;
                float o0 = ws * acc[mt][nt][rr * 2 + 0] + zs * base[(col    ) * 2];
                float o1 = ws * acc[mt][nt][rr * 2 + 1] + zs * base[(col + 1) * 2];
                *(float2*)(dstb + (size_t)r * Hh + col) = make_float2(o0, o1);
            }
        }
    }
}

// ---------------------------------------------------------------------------
extern "C" void kernel_launch(void* const* d_in, const int* in_sizes, int n_in,
                              void* d_out, int out_size) {
    const void*  inputs = nullptr;
    const float* A      = nullptr;
    const float* emb    = nullptr;

    for (int i = 0; i < n_in; ++i) {
        if (in_sizes[i] == Bsz * Nn)               inputs = d_in[i];
        else if (in_sizes[i] == Bsz * Nn * 2 * Nn) A      = (const float*)d_in[i];
        else if (in_sizes[i] == NNODE * Hh)        emb    = (const float*)d_in[i];
    }
    if (!inputs) inputs = d_in[0];
    if (!A)      A      = (const float*)d_in[1];
    if (!emb)    emb    = (const float*)d_in[2];

    float* out = (float*)d_out;

    static bool attr_set = false;
    const int smem_bytes = SMEM_FLOATS * sizeof(float);   // 71,680 B
    if (!attr_set) {
        cudaFuncSetAttribute(sgc_fused, cudaFuncAttributeMaxDynamicSharedMemorySize,
                             smem_bytes);
        attr_set = true;
    }

    prep_kernel<<<dim3(16, Bsz), 256>>>(A);
    sgc_fused<<<dim3(2, Bsz), 256, smem_bytes>>>(inputs, emb, out);
}